// round 2
// baseline (speedup 1.0000x reference)
#include <cuda_runtime.h>
#include <math.h>

// ---------------------------------------------------------------------------
// Problem constants
//   x:   (B=512, C=1024, 7, 7)  -> N = 49 tokens/window, M = B*N = 25088
//   Q = (xt @ Wq^T + bq) * D^-0.5 ; KV = xt @ Wkv^T + bkv
//   attn = softmax-mix(q k^T + rpb) ; o = attn v ; y = o @ Wproj^T + bproj
// ---------------------------------------------------------------------------
#define BD   512
#define CD   1024
#define NTOK 49
#define HH   8
#define DD   128
#define MM   (BD * NTOK)          // 25088
#define KK   1024

// Device scratch (allocation-free rule: __device__ globals)
__device__ float g_xt [MM * CD];          // (M, C)      xt
__device__ float g_qkv[MM * 3 * CD];      // (M, 3C)     [q | k | v]
__device__ float g_o1 [MM * CD];          // (M, C)      attention output
__device__ float g_o2 [MM * CD];          // (M, C)      proj output

// ---------------------------------------------------------------------------
// Helpers
// ---------------------------------------------------------------------------
__device__ __forceinline__ unsigned f2tf(float x) {
    unsigned r;
    asm("cvt.rna.tf32.f32 %0, %1;" : "=r"(r) : "f"(x));
    return r;
}

__device__ __forceinline__ void mma8(float* c, const unsigned* a, const unsigned* b) {
    asm volatile(
        "mma.sync.aligned.m16n8k8.row.col.f32.tf32.tf32.f32 "
        "{%0,%1,%2,%3}, {%4,%5,%6,%7}, {%8,%9}, {%0,%1,%2,%3};"
        : "+f"(c[0]), "+f"(c[1]), "+f"(c[2]), "+f"(c[3])
        : "r"(a[0]), "r"(a[1]), "r"(a[2]), "r"(a[3]), "r"(b[0]), "r"(b[1]));
}

// ---------------------------------------------------------------------------
// Kernel 1: x (B, C, N) -> xt (M = B*N, C)
// ---------------------------------------------------------------------------
__global__ __launch_bounds__(256) void transpose_in(const float* __restrict__ x) {
    __shared__ float t[32][51];
    int b  = blockIdx.x;
    int c0 = blockIdx.y * 32;
    const float* xp = x + (size_t)b * CD * NTOK + (size_t)c0 * NTOK;
    for (int idx = threadIdx.x; idx < 32 * NTOK; idx += 256) {
        int c = idx / NTOK, n = idx - c * NTOK;
        t[c][n] = xp[c * NTOK + n];
    }
    __syncthreads();
    for (int idx = threadIdx.x; idx < 32 * NTOK; idx += 256) {
        int n = idx >> 5, c = idx & 31;
        g_xt[(size_t)(b * NTOK + n) * CD + c0 + c] = t[c][n];
    }
}

// ---------------------------------------------------------------------------
// Kernel 2: generic GEMM  C[m, colOff+n] = (A[m,:] . W[n,:] + bias[n]) * scale
//   A: (M, 1024) row-major fp32 ; W: (Nout, 1024) row-major fp32
//   tile 128(m) x 64(n) x 32(k), 8 warps (4x2), warp tile 32x32,
//   mma.sync m16n8k8 tf32, register-prefetch double buffering.
//   M = 25088 = 196*128, Nout multiple of 64, K = 1024 = 32*32 (no edges).
// ---------------------------------------------------------------------------
__global__ __launch_bounds__(256) void gemm_tf32(
    const float* __restrict__ A, const float* __restrict__ W,
    const float* __restrict__ bias, float* __restrict__ Co,
    int ldc, int colOff, float scale)
{
    __shared__ unsigned As[128 * 36];
    __shared__ unsigned Bs[64 * 36];

    const int tid  = threadIdx.x;
    const int m0   = blockIdx.x * 128;
    const int n0   = blockIdx.y * 64;
    const int lrow = tid >> 3;          // 0..31
    const int lc4  = (tid & 7) * 4;     // 0..28 step 4

    const float* Ab = A + (size_t)m0 * KK;
    const float* Wb = W + (size_t)n0 * KK;

    const int warp = tid >> 5, lane = tid & 31;
    const int wm = warp >> 1, wn = warp & 1;
    const int g = lane >> 2, t4 = lane & 3;

    float4 ra[4];
    float4 rb[2];

    float acc[2][4][4];
#pragma unroll
    for (int mi = 0; mi < 2; mi++)
#pragma unroll
        for (int ni = 0; ni < 4; ni++)
#pragma unroll
            for (int q = 0; q < 4; q++) acc[mi][ni][q] = 0.f;

    // prologue load kt=0
#pragma unroll
    for (int i = 0; i < 4; i++)
        ra[i] = *(const float4*)(Ab + (size_t)(lrow + i * 32) * KK + lc4);
#pragma unroll
    for (int i = 0; i < 2; i++)
        rb[i] = *(const float4*)(Wb + (size_t)(lrow + i * 32) * KK + lc4);

#pragma unroll
    for (int i = 0; i < 4; i++) {
        uint4 u = { f2tf(ra[i].x), f2tf(ra[i].y), f2tf(ra[i].z), f2tf(ra[i].w) };
        *(uint4*)&As[(lrow + i * 32) * 36 + lc4] = u;
    }
#pragma unroll
    for (int i = 0; i < 2; i++) {
        uint4 u = { f2tf(rb[i].x), f2tf(rb[i].y), f2tf(rb[i].z), f2tf(rb[i].w) };
        *(uint4*)&Bs[(lrow + i * 32) * 36 + lc4] = u;
    }
    __syncthreads();

    for (int kt = 0; kt < 32; kt++) {
        if (kt < 31) {
            int ko = (kt + 1) * 32 + lc4;
#pragma unroll
            for (int i = 0; i < 4; i++)
                ra[i] = *(const float4*)(Ab + (size_t)(lrow + i * 32) * KK + ko);
#pragma unroll
            for (int i = 0; i < 2; i++)
                rb[i] = *(const float4*)(Wb + (size_t)(lrow + i * 32) * KK + ko);
        }

#pragma unroll
        for (int k8 = 0; k8 < 4; k8++) {
            unsigned af[2][4], bf[4][2];
#pragma unroll
            for (int mi = 0; mi < 2; mi++) {
                int rbse = wm * 32 + mi * 16;
                af[mi][0] = As[(rbse + g)     * 36 + k8 * 8 + t4];
                af[mi][1] = As[(rbse + g + 8) * 36 + k8 * 8 + t4];
                af[mi][2] = As[(rbse + g)     * 36 + k8 * 8 + t4 + 4];
                af[mi][3] = As[(rbse + g + 8) * 36 + k8 * 8 + t4 + 4];
            }
#pragma unroll
            for (int ni = 0; ni < 4; ni++) {
                int nb = wn * 32 + ni * 8;
                bf[ni][0] = Bs[(nb + g) * 36 + k8 * 8 + t4];
                bf[ni][1] = Bs[(nb + g) * 36 + k8 * 8 + t4 + 4];
            }
#pragma unroll
            for (int mi = 0; mi < 2; mi++)
#pragma unroll
                for (int ni = 0; ni < 4; ni++)
                    mma8(acc[mi][ni], af[mi], bf[ni]);
        }
        __syncthreads();

        if (kt < 31) {
#pragma unroll
            for (int i = 0; i < 4; i++) {
                uint4 u = { f2tf(ra[i].x), f2tf(ra[i].y), f2tf(ra[i].z), f2tf(ra[i].w) };
                *(uint4*)&As[(lrow + i * 32) * 36 + lc4] = u;
            }
#pragma unroll
            for (int i = 0; i < 2; i++) {
                uint4 u = { f2tf(rb[i].x), f2tf(rb[i].y), f2tf(rb[i].z), f2tf(rb[i].w) };
                *(uint4*)&Bs[(lrow + i * 32) * 36 + lc4] = u;
            }
            __syncthreads();
        }
    }

    // epilogue
#pragma unroll
    for (int mi = 0; mi < 2; mi++) {
#pragma unroll
        for (int ni = 0; ni < 4; ni++) {
            int row = m0 + wm * 32 + mi * 16 + g;
            int col = n0 + wn * 32 + ni * 8 + t4 * 2;
            float b0 = bias[col], b1 = bias[col + 1];
            float2 v0 = { (acc[mi][ni][0] + b0) * scale, (acc[mi][ni][1] + b1) * scale };
            float2 v1 = { (acc[mi][ni][2] + b0) * scale, (acc[mi][ni][3] + b1) * scale };
            *(float2*)&Co[(size_t)row       * ldc + colOff + col] = v0;
            *(float2*)&Co[(size_t)(row + 8) * ldc + colOff + col] = v1;
        }
    }
}

// ---------------------------------------------------------------------------
// Kernel 3: windowed attention per (b, h). 256 threads/block, 4096 blocks.
//   smem: q,k,v (49 x 128, row stride 132) + S (49x49) + rpb slice (169)
// ---------------------------------------------------------------------------
#define QKV_PITCH 132
#define ATTN_SMEM_FLOATS (3 * NTOK * QKV_PITCH + NTOK * NTOK + 169)
#define ATTN_SMEM_BYTES  (ATTN_SMEM_FLOATS * 4)

__global__ __launch_bounds__(256) void attn_kernel(const float* __restrict__ rpb_table,
                                                   const float* __restrict__ w_mix)
{
    extern __shared__ float sm[];
    float* qs = sm;
    float* ks = qs + NTOK * QKV_PITCH;
    float* vs = ks + NTOK * QKV_PITCH;
    float* ss = vs + NTOK * QKV_PITCH;
    float* rp = ss + NTOK * NTOK;

    int bh = blockIdx.x;
    int b = bh >> 3, h = bh & 7;
    int tid = threadIdx.x;

    // branch weights (uniform; computed before barriers, no divergence)
    float wa = w_mix[0], wb = w_mix[1];
    float wmx = fmaxf(wa, wb);
    float ea = __expf(wa - wmx), eb = __expf(wb - wmx);
    float wden = 1.f / (ea + eb);
    float w0 = ea * wden, w1 = eb * wden;

    size_t base = (size_t)(b * NTOK) * (3 * CD) + h * DD;
    for (int idx = tid; idx < NTOK * DD; idx += 256) {
        int i = idx >> 7, d = idx & 127;
        size_t r = base + (size_t)i * (3 * CD) + d;
        qs[i * QKV_PITCH + d] = g_qkv[r];
        ks[i * QKV_PITCH + d] = g_qkv[r + CD];
        vs[i * QKV_PITCH + d] = g_qkv[r + 2 * CD];
    }
    for (int idx = tid; idx < 169; idx += 256) rp[idx] = rpb_table[idx * HH + h];
    __syncthreads();

    // S = q k^T + rpb
    for (int e = tid; e < NTOK * NTOK; e += 256) {
        int i = e / NTOK, j = e - i * NTOK;
        const float4* qq = (const float4*)(qs + i * QKV_PITCH);
        const float4* kk = (const float4*)(ks + j * QKV_PITCH);
        float a0 = 0.f, a1 = 0.f, a2 = 0.f, a3 = 0.f;
#pragma unroll
        for (int t = 0; t < DD / 4; t++) {
            float4 xq = qq[t], xk = kk[t];
            a0 += xq.x * xk.x; a1 += xq.y * xk.y;
            a2 += xq.z * xk.z; a3 += xq.w * xk.w;
        }
        int ri = i / 7, ci = i - 7 * ri;
        int rj = j / 7, cj = j - 7 * rj;
        ss[e] = (a0 + a1) + (a2 + a3) + rp[(ri - rj + 6) * 13 + (ci - cj + 6)];
    }
    __syncthreads();

    // row softmax + relu^2 mix  (one warp per row)
    int warp = tid >> 5, lane = tid & 31;
    for (int r = warp; r < NTOK; r += 8) {
        float x0 = ss[r * NTOK + lane];
        bool v1 = (lane + 32) < NTOK;
        float x1 = v1 ? ss[r * NTOK + lane + 32] : -1e30f;
        float m = fmaxf(x0, x1);
#pragma unroll
        for (int o = 16; o > 0; o >>= 1) m = fmaxf(m, __shfl_xor_sync(0xffffffffu, m, o));
        float p0 = __expf(x0 - m);
        float p1 = v1 ? __expf(x1 - m) : 0.f;
        float s = p0 + p1;
#pragma unroll
        for (int o = 16; o > 0; o >>= 1) s += __shfl_xor_sync(0xffffffffu, s, o);
        float inv = 1.f / s;
        float r0 = fmaxf(x0, 0.f), r1 = fmaxf(x1, 0.f);
        ss[r * NTOK + lane] = w0 * p0 * inv + w1 * r0 * r0;
        if (v1) ss[r * NTOK + lane + 32] = w0 * p1 * inv + w1 * r1 * r1;
    }
    __syncthreads();

    // O = attn @ v
    for (int idx = tid; idx < NTOK * DD; idx += 256) {
        int i = idx >> 7, d = idx & 127;
        const float* sr = ss + i * NTOK;
        float acc = 0.f;
#pragma unroll
        for (int j = 0; j < NTOK; j++) acc += sr[j] * vs[j * QKV_PITCH + d];
        g_o1[(size_t)(b * NTOK + i) * CD + h * DD + d] = acc;
    }
}

// ---------------------------------------------------------------------------
// Kernel 4: o2 (M, C) -> y (B, C, N)
// ---------------------------------------------------------------------------
__global__ __launch_bounds__(256) void transpose_out(float* __restrict__ y) {
    __shared__ float t[NTOK][33];
    int b  = blockIdx.x;
    int c0 = blockIdx.y * 32;
    for (int idx = threadIdx.x; idx < NTOK * 32; idx += 256) {
        int n = idx >> 5, c = idx & 31;
        t[n][c] = g_o2[(size_t)(b * NTOK + n) * CD + c0 + c];
    }
    __syncthreads();
    float* yp = y + (size_t)b * CD * NTOK + (size_t)c0 * NTOK;
    for (int idx = threadIdx.x; idx < 32 * NTOK; idx += 256) {
        int c = idx / NTOK, n = idx - c * NTOK;
        yp[c * NTOK + n] = t[n][c];
    }
}

// ---------------------------------------------------------------------------
// Launch
// ---------------------------------------------------------------------------
extern "C" void kernel_launch(void* const* d_in, const int* in_sizes, int n_in,
                              void* d_out, int out_size)
{
    const float* x     = (const float*)d_in[0];
    const float* Wq    = (const float*)d_in[1];
    const float* bq    = (const float*)d_in[2];
    const float* Wkv   = (const float*)d_in[3];
    const float* bkv   = (const float*)d_in[4];
    const float* rpb   = (const float*)d_in[5];
    const float* wmix  = (const float*)d_in[6];
    const float* Wproj = (const float*)d_in[7];
    const float* bproj = (const float*)d_in[8];
    float* y = (float*)d_out;

    void *p_xt, *p_qkv, *p_o1, *p_o2;
    cudaGetSymbolAddress(&p_xt,  g_xt);
    cudaGetSymbolAddress(&p_qkv, g_qkv);
    cudaGetSymbolAddress(&p_o1,  g_o1);
    cudaGetSymbolAddress(&p_o2,  g_o2);

    cudaFuncSetAttribute(attn_kernel, cudaFuncAttributeMaxDynamicSharedMemorySize,
                         ATTN_SMEM_BYTES);

    const float scale = 0.08838834764831845f;   // 128^-0.5

    transpose_in<<<dim3(BD, CD / 32), 256>>>(x);

    // q  -> qkv[:, 0:1024]   (scale applied to (x@Wq^T + bq))
    gemm_tf32<<<dim3(MM / 128, CD / 64), 256>>>(
        (const float*)p_xt, Wq, bq, (float*)p_qkv, 3 * CD, 0, scale);
    // kv -> qkv[:, 1024:3072]
    gemm_tf32<<<dim3(MM / 128, 2 * CD / 64), 256>>>(
        (const float*)p_xt, Wkv, bkv, (float*)p_qkv, 3 * CD, CD, 1.0f);

    attn_kernel<<<BD * HH, 256, ATTN_SMEM_BYTES>>>(rpb, wmix);

    gemm_tf32<<<dim3(MM / 128, CD / 64), 256>>>(
        (const float*)p_o1, Wproj, bproj, (float*)p_o2, CD, 0, 1.0f);

    transpose_out<<<dim3(BD, CD / 32), 256>>>(y);
}

// round 3
// speedup vs baseline: 1.2436x; 1.2436x over previous
#include <cuda_runtime.h>
#include <math.h>

// ---------------------------------------------------------------------------
//   x: (B=512, C=1024, 7, 7) -> N = 49 tokens/window, M = B*N = 25088
//   Q = (xt @ Wq^T + bq) * D^-0.5 ; KV = xt @ Wkv^T + bkv
//   attn = mix(softmax, relu^2)(q k^T + rpb) ; o = attn v ; y = o @ Wproj^T + b
// ---------------------------------------------------------------------------
#define BD   512
#define CD   1024
#define NTOK 49
#define HH   8
#define DD   128
#define MM   (BD * NTOK)          // 25088
#define KK   1024

// Device scratch (allocation-free rule: __device__ globals)
__device__ float g_xt [MM * CD];          // (M, C)   xt, tf32-rounded
__device__ float g_qkv[MM * 3 * CD];      // (M, 3C)  [q | k | v]  fp32
__device__ float g_o1 [MM * CD];          // (M, C)   attn out, tf32-rounded
__device__ float g_o2 [MM * CD];          // (M, C)   proj out fp32
__device__ float g_wq [CD * KK];          // tf32-rounded weights
__device__ float g_wkv[2 * CD * KK];
__device__ float g_wp [CD * KK];

// ---------------------------------------------------------------------------
// Helpers
// ---------------------------------------------------------------------------
__device__ __forceinline__ unsigned f2tf(float x) {
    unsigned r;
    asm("cvt.rna.tf32.f32 %0, %1;" : "=r"(r) : "f"(x));
    return r;
}

__device__ __forceinline__ void mma8(float* c, const unsigned* a, const unsigned* b) {
    asm volatile(
        "mma.sync.aligned.m16n8k8.row.col.f32.tf32.tf32.f32 "
        "{%0,%1,%2,%3}, {%4,%5,%6,%7}, {%8,%9}, {%0,%1,%2,%3};"
        : "+f"(c[0]), "+f"(c[1]), "+f"(c[2]), "+f"(c[3])
        : "r"(a[0]), "r"(a[1]), "r"(a[2]), "r"(a[3]), "r"(b[0]), "r"(b[1]));
}

__device__ __forceinline__ void cpa16(unsigned dst, const float* src) {
    asm volatile("cp.async.cg.shared.global [%0], [%1], 16;\n" :: "r"(dst), "l"(src));
}
__device__ __forceinline__ void cpa_commit() {
    asm volatile("cp.async.commit_group;\n");
}
__device__ __forceinline__ void cpa_wait1() {
    asm volatile("cp.async.wait_group 1;\n");
}

// ---------------------------------------------------------------------------
// Kernel 0: elementwise f32 -> tf32(rna) copy (weights prep)
// ---------------------------------------------------------------------------
__global__ __launch_bounds__(256) void cvt_tf32(const float* __restrict__ src,
                                                float* __restrict__ dst, int n4) {
    int i = blockIdx.x * 256 + threadIdx.x;
    if (i < n4) {
        float4 v = ((const float4*)src)[i];
        uint4 u = { f2tf(v.x), f2tf(v.y), f2tf(v.z), f2tf(v.w) };
        ((uint4*)dst)[i] = u;
    }
}

// ---------------------------------------------------------------------------
// Kernel 1: x (B, C, N) -> xt (M, C), tf32-rounded
// ---------------------------------------------------------------------------
__global__ __launch_bounds__(256) void transpose_in(const float* __restrict__ x) {
    __shared__ float t[32][51];
    int b  = blockIdx.x;
    int c0 = blockIdx.y * 32;
    const float* xp = x + (size_t)b * CD * NTOK + (size_t)c0 * NTOK;
    for (int idx = threadIdx.x; idx < 32 * NTOK; idx += 256) {
        int c = idx / NTOK, n = idx - c * NTOK;
        t[c][n] = xp[c * NTOK + n];
    }
    __syncthreads();
    for (int idx = threadIdx.x; idx < 32 * NTOK; idx += 256) {
        int n = idx >> 5, c = idx & 31;
        ((unsigned*)g_xt)[(size_t)(b * NTOK + n) * CD + c0 + c] = f2tf(t[c][n]);
    }
}

// ---------------------------------------------------------------------------
// Kernel 2: GEMM  C[m, colOff+n] = A[m,:] . W[n,:] + bias[n]
//   A, W already tf32-rounded fp32 bits. 128x128x32 tile, 3-buffer cp.async,
//   8 warps (2x4), warp tile 64x32, mma m16n8k8 tf32.
// ---------------------------------------------------------------------------
#define BM 128
#define BN 128
#define BK 32
#define GP 36                       // smem pitch (conflict-free frag loads)
#define TILE_F (BM * GP)            // floats per A (or B) tile
#define STG_F  (2 * TILE_F)         // floats per stage
#define NKT (KK / BK)               // 32

__global__ __launch_bounds__(256) void gemm_tf32(
    const float* __restrict__ A, const float* __restrict__ W,
    const float* __restrict__ bias, float* __restrict__ Co,
    int ldc, int colOff)
{
    extern __shared__ float dsm[];                 // 3 stages * 2 tiles * 128*36

    const int tid  = threadIdx.x;
    const int m0   = blockIdx.x * BM;
    const int n0   = blockIdx.y * BN;
    const int lrow = tid >> 3;                     // 0..31
    const int lc4  = (tid & 7) * 4;                // 0..28 step 4

    const float* Ab = A + (size_t)m0 * KK + lrow * KK + lc4;
    const float* Wb = W + (size_t)n0 * KK + lrow * KK + lc4;

    // smem byte addresses for this thread's cp.async destinations
    unsigned smBase = (unsigned)__cvta_generic_to_shared(dsm);
    unsigned aDst = smBase + (lrow * GP + lc4) * 4;
    unsigned bDst = aDst + TILE_F * 4;

    const int warp = tid >> 5, lane = tid & 31;
    const int wm = warp >> 2, wn = warp & 3;       // 2 x 4
    const int g = lane >> 2, t4 = lane & 3;

    float acc[4][4][4];
#pragma unroll
    for (int mi = 0; mi < 4; mi++)
#pragma unroll
        for (int ni = 0; ni < 4; ni++)
#pragma unroll
            for (int q = 0; q < 4; q++) acc[mi][ni][q] = 0.f;

    // prologue: stages 0, 1
#pragma unroll
    for (int s = 0; s < 2; s++) {
        unsigned off = s * STG_F * 4;
        const float* ap = Ab + s * BK;
        const float* wp = Wb + s * BK;
#pragma unroll
        for (int i = 0; i < 4; i++) {
            cpa16(aDst + off + i * 32 * GP * 4, ap + (size_t)i * 32 * KK);
            cpa16(bDst + off + i * 32 * GP * 4, wp + (size_t)i * 32 * KK);
        }
        cpa_commit();
    }

    int stage = 0;
    for (int kt = 0; kt < NKT; kt++) {
        cpa_wait1();                 // stage kt resident
        __syncthreads();

        // prefetch stage kt+2 into buffer (kt+2)%3 (consumed at iter kt-1)
        if (kt + 2 < NKT) {
            int ps = stage + 2; if (ps >= 3) ps -= 3;
            unsigned off = ps * STG_F * 4;
            const float* ap = Ab + (kt + 2) * BK;
            const float* wp = Wb + (kt + 2) * BK;
#pragma unroll
            for (int i = 0; i < 4; i++) {
                cpa16(aDst + off + i * 32 * GP * 4, ap + (size_t)i * 32 * KK);
                cpa16(bDst + off + i * 32 * GP * 4, wp + (size_t)i * 32 * KK);
            }
        }
        cpa_commit();

        const unsigned* As = (const unsigned*)(dsm + stage * STG_F);
        const unsigned* Bs = As + TILE_F;

#pragma unroll
        for (int k8 = 0; k8 < 4; k8++) {
            unsigned af[4][4], bf[4][2];
#pragma unroll
            for (int mi = 0; mi < 4; mi++) {
                int rb = wm * 64 + mi * 16;
                af[mi][0] = As[(rb + g)     * GP + k8 * 8 + t4];
                af[mi][1] = As[(rb + g + 8) * GP + k8 * 8 + t4];
                af[mi][2] = As[(rb + g)     * GP + k8 * 8 + t4 + 4];
                af[mi][3] = As[(rb + g + 8) * GP + k8 * 8 + t4 + 4];
            }
#pragma unroll
            for (int ni = 0; ni < 4; ni++) {
                int nb = wn * 32 + ni * 8;
                bf[ni][0] = Bs[(nb + g) * GP + k8 * 8 + t4];
                bf[ni][1] = Bs[(nb + g) * GP + k8 * 8 + t4 + 4];
            }
#pragma unroll
            for (int mi = 0; mi < 4; mi++)
#pragma unroll
                for (int ni = 0; ni < 4; ni++)
                    mma8(acc[mi][ni], af[mi], bf[ni]);
        }
        stage++; if (stage >= 3) stage = 0;
    }

    // epilogue: + bias, fp32 out
#pragma unroll
    for (int mi = 0; mi < 4; mi++) {
#pragma unroll
        for (int ni = 0; ni < 4; ni++) {
            int row = m0 + wm * 64 + mi * 16 + g;
            int col = n0 + wn * 32 + ni * 8 + t4 * 2;
            float b0 = bias[col], b1 = bias[col + 1];
            float2 v0 = { acc[mi][ni][0] + b0, acc[mi][ni][1] + b1 };
            float2 v1 = { acc[mi][ni][2] + b0, acc[mi][ni][3] + b1 };
            *(float2*)&Co[(size_t)row       * ldc + colOff + col] = v0;
            *(float2*)&Co[(size_t)(row + 8) * ldc + colOff + col] = v1;
        }
    }
}

// ---------------------------------------------------------------------------
// Kernel 3: windowed attention per (b, h). 256 threads, 4096 blocks.
// ---------------------------------------------------------------------------
#define QKV_PITCH 132
#define ATTN_SMEM_FLOATS (3 * NTOK * QKV_PITCH + NTOK * NTOK + 169)
#define ATTN_SMEM_BYTES  (ATTN_SMEM_FLOATS * 4)

__global__ __launch_bounds__(256) void attn_kernel(const float* __restrict__ rpb_table,
                                                   const float* __restrict__ w_mix)
{
    extern __shared__ float sm[];
    float* qs = sm;
    float* ks = qs + NTOK * QKV_PITCH;
    float* vs = ks + NTOK * QKV_PITCH;
    float* ss = vs + NTOK * QKV_PITCH;
    float* rp = ss + NTOK * NTOK;

    int bh = blockIdx.x;
    int b = bh >> 3, h = bh & 7;
    int tid = threadIdx.x;

    // mix weights (uniform)
    float wa = w_mix[0], wb = w_mix[1];
    float wmx = fmaxf(wa, wb);
    float ea = __expf(wa - wmx), eb = __expf(wb - wmx);
    float wden = 1.f / (ea + eb);
    float w0 = ea * wden, w1 = eb * wden;

    const float scale = 0.08838834764831845f;      // 128^-0.5 (applied to q)

    size_t base = (size_t)(b * NTOK) * (3 * CD) + h * DD;
    for (int idx = tid; idx < NTOK * DD; idx += 256) {
        int i = idx >> 7, d = idx & 127;
        size_t r = base + (size_t)i * (3 * CD) + d;
        qs[i * QKV_PITCH + d] = g_qkv[r] * scale;
        ks[i * QKV_PITCH + d] = g_qkv[r + CD];
        vs[i * QKV_PITCH + d] = g_qkv[r + 2 * CD];
    }
    for (int idx = tid; idx < 169; idx += 256) rp[idx] = rpb_table[idx * HH + h];
    __syncthreads();

    // --- S = q k^T + rpb : 4x4 register tiles, 13x13 tile grid (169 threads)
    if (tid < 169) {
        int ti = tid / 13, tj = tid % 13;
        int ib = ti * 4, jb = tj * 4;
        int ri0 = (ib    < 49) ? ib     : 48;
        int ri1 = (ib + 1 < 49) ? ib + 1 : 48;
        int ri2 = (ib + 2 < 49) ? ib + 2 : 48;
        int ri3 = (ib + 3 < 49) ? ib + 3 : 48;
        int rj0 = (jb    < 49) ? jb     : 48;
        int rj1 = (jb + 1 < 49) ? jb + 1 : 48;
        int rj2 = (jb + 2 < 49) ? jb + 2 : 48;
        int rj3 = (jb + 3 < 49) ? jb + 3 : 48;
        const float4* q0 = (const float4*)(qs + ri0 * QKV_PITCH);
        const float4* q1 = (const float4*)(qs + ri1 * QKV_PITCH);
        const float4* q2 = (const float4*)(qs + ri2 * QKV_PITCH);
        const float4* q3 = (const float4*)(qs + ri3 * QKV_PITCH);
        const float4* k0 = (const float4*)(ks + rj0 * QKV_PITCH);
        const float4* k1 = (const float4*)(ks + rj1 * QKV_PITCH);
        const float4* k2 = (const float4*)(ks + rj2 * QKV_PITCH);
        const float4* k3 = (const float4*)(ks + rj3 * QKV_PITCH);

        float acc[4][4];
#pragma unroll
        for (int a = 0; a < 4; a++)
#pragma unroll
            for (int c = 0; c < 4; c++) acc[a][c] = 0.f;

#pragma unroll 4
        for (int t = 0; t < 32; t++) {
            float4 qr[4] = { q0[t], q1[t], q2[t], q3[t] };
            float4 kr[4] = { k0[t], k1[t], k2[t], k3[t] };
#pragma unroll
            for (int a = 0; a < 4; a++)
#pragma unroll
                for (int c = 0; c < 4; c++)
                    acc[a][c] += qr[a].x * kr[c].x + qr[a].y * kr[c].y
                               + qr[a].z * kr[c].z + qr[a].w * kr[c].w;
        }
#pragma unroll
        for (int a = 0; a < 4; a++) {
            int i = ib + a;
            if (i < 49) {
                int ri = i / 7, ci = i - 7 * ri;
#pragma unroll
                for (int c = 0; c < 4; c++) {
                    int j = jb + c;
                    if (j < 49) {
                        int rj = j / 7, cj = j - 7 * rj;
                        ss[i * 49 + j] = acc[a][c]
                                       + rp[(ri - rj + 6) * 13 + (ci - cj + 6)];
                    }
                }
            }
        }
    }
    __syncthreads();

    // --- row softmax + relu^2 mix (one warp per row)
    int warp = tid >> 5, lane = tid & 31;
    for (int r = warp; r < NTOK; r += 8) {
        float x0 = ss[r * NTOK + lane];
        bool v1 = (lane + 32) < NTOK;
        float x1 = v1 ? ss[r * NTOK + lane + 32] : -1e30f;
        float m = fmaxf(x0, x1);
#pragma unroll
        for (int o = 16; o > 0; o >>= 1) m = fmaxf(m, __shfl_xor_sync(0xffffffffu, m, o));
        float p0 = __expf(x0 - m);
        float p1 = v1 ? __expf(x1 - m) : 0.f;
        float s = p0 + p1;
#pragma unroll
        for (int o = 16; o > 0; o >>= 1) s += __shfl_xor_sync(0xffffffffu, s, o);
        float inv = 1.f / s;
        float r0 = fmaxf(x0, 0.f), r1 = fmaxf(x1, 0.f);
        ss[r * NTOK + lane] = w0 * p0 * inv + w1 * r0 * r0;
        if (v1) ss[r * NTOK + lane + 32] = w0 * p1 * inv + w1 * r1 * r1;
    }
    __syncthreads();

    // --- O = attn @ v : thread owns column d, 7-row chunks; v reused across rows
    {
        int d = tid & 127, half = tid >> 7;
        unsigned* o1u = (unsigned*)g_o1;
        size_t obase = (size_t)(b * NTOK) * CD + h * DD + d;
        for (int c = half; c < 7; c += 2) {
            float acc[7] = {0.f, 0.f, 0.f, 0.f, 0.f, 0.f, 0.f};
            const float* sbase = ss + (c * 7) * 49;
#pragma unroll 7
            for (int j = 0; j < 49; j++) {
                float vj = vs[j * QKV_PITCH + d];
#pragma unroll
                for (int ii = 0; ii < 7; ii++)
                    acc[ii] += sbase[ii * 49 + j] * vj;
            }
#pragma unroll
            for (int ii = 0; ii < 7; ii++)
                o1u[obase + (size_t)(c * 7 + ii) * CD] = f2tf(acc[ii]);
        }
    }
}

// ---------------------------------------------------------------------------
// Kernel 4: o2 (M, C) -> y (B, C, N)
// ---------------------------------------------------------------------------
__global__ __launch_bounds__(256) void transpose_out(float* __restrict__ y) {
    __shared__ float t[NTOK][33];
    int b  = blockIdx.x;
    int c0 = blockIdx.y * 32;
    for (int idx = threadIdx.x; idx < NTOK * 32; idx += 256) {
        int n = idx >> 5, c = idx & 31;
        t[n][c] = g_o2[(size_t)(b * NTOK + n) * CD + c0 + c];
    }
    __syncthreads();
    float* yp = y + (size_t)b * CD * NTOK + (size_t)c0 * NTOK;
    for (int idx = threadIdx.x; idx < 32 * NTOK; idx += 256) {
        int c = idx / NTOK, n = idx - c * NTOK;
        yp[c * NTOK + n] = t[n][c];
    }
}

// ---------------------------------------------------------------------------
// Launch
// ---------------------------------------------------------------------------
#define GEMM_SMEM (3 * STG_F * 4)          // 110592 bytes

extern "C" void kernel_launch(void* const* d_in, const int* in_sizes, int n_in,
                              void* d_out, int out_size)
{
    const float* x     = (const float*)d_in[0];
    const float* Wq    = (const float*)d_in[1];
    const float* bq    = (const float*)d_in[2];
    const float* Wkv   = (const float*)d_in[3];
    const float* bkv   = (const float*)d_in[4];
    const float* rpb   = (const float*)d_in[5];
    const float* wmix  = (const float*)d_in[6];
    const float* Wproj = (const float*)d_in[7];
    const float* bproj = (const float*)d_in[8];
    float* y = (float*)d_out;

    void *p_xt, *p_qkv, *p_o1, *p_o2, *p_wq, *p_wkv, *p_wp;
    cudaGetSymbolAddress(&p_xt,  g_xt);
    cudaGetSymbolAddress(&p_qkv, g_qkv);
    cudaGetSymbolAddress(&p_o1,  g_o1);
    cudaGetSymbolAddress(&p_o2,  g_o2);
    cudaGetSymbolAddress(&p_wq,  g_wq);
    cudaGetSymbolAddress(&p_wkv, g_wkv);
    cudaGetSymbolAddress(&p_wp,  g_wp);

    cudaFuncSetAttribute(attn_kernel, cudaFuncAttributeMaxDynamicSharedMemorySize,
                         ATTN_SMEM_BYTES);
    cudaFuncSetAttribute(gemm_tf32, cudaFuncAttributeMaxDynamicSharedMemorySize,
                         GEMM_SMEM);

    // weight prep (tf32 rna) + input transpose
    cvt_tf32<<<(CD * KK / 4 + 255) / 256, 256>>>(Wq,    (float*)p_wq,  CD * KK / 4);
    cvt_tf32<<<(2 * CD * KK / 4 + 255) / 256, 256>>>(Wkv, (float*)p_wkv, 2 * CD * KK / 4);
    cvt_tf32<<<(CD * KK / 4 + 255) / 256, 256>>>(Wproj, (float*)p_wp,  CD * KK / 4);
    transpose_in<<<dim3(BD, CD / 32), 256>>>(x);

    // q -> qkv[:, 0:1024] ; kv -> qkv[:, 1024:3072]
    gemm_tf32<<<dim3(MM / BM, CD / BN), 256, GEMM_SMEM>>>(
        (const float*)p_xt, (const float*)p_wq, bq, (float*)p_qkv, 3 * CD, 0);
    gemm_tf32<<<dim3(MM / BM, 2 * CD / BN), 256, GEMM_SMEM>>>(
        (const float*)p_xt, (const float*)p_wkv, bkv, (float*)p_qkv, 3 * CD, CD);

    attn_kernel<<<BD * HH, 256, ATTN_SMEM_BYTES>>>(rpb, wmix);

    gemm_tf32<<<dim3(MM / BM, CD / BN), 256, GEMM_SMEM>>>(
        (const float*)p_o1, (const float*)p_wp, bproj, (float*)p_o2, CD, 0);

    transpose_out<<<dim3(BD, CD / 32), 256>>>(y);
}